// round 1
// baseline (speedup 1.0000x reference)
#include <cuda_runtime.h>
#include <cstdint>

#define DI __device__ __forceinline__

static constexpr int B_ = 4, H_ = 8, S_ = 2048, D_ = 1024, KQ_ = 128;

// ---------------- scratch (device globals; no allocations allowed) ----------------
__device__ float g_M[(size_t)H_ * D_ * D_];            //  32 MB  M_h = Wv_h @ Wo_h
__device__ float g_cvec[D_];                           //  bias vector folded through Wo
__device__ float g_cpart[32 * D_];
__device__ float g_Q[(size_t)B_ * H_ * S_ * KQ_];      //  32 MB
__device__ float g_Kb[(size_t)B_ * H_ * S_ * KQ_];     //  32 MB
__device__ float g_U[(size_t)B_ * H_ * S_ * D_];       // 256 MB  U = z @ M_h
__device__ float g_P[(size_t)B_ * H_ * S_ * S_];       // 512 MB  scores / attn
__device__ float g_O[(size_t)B_ * H_ * S_ * D_];       // 256 MB  per-head partial out

// ---------------- helpers ----------------
DI float tf32r(float x) {
    uint32_t u;
    asm("cvt.rna.tf32.f32 %0, %1;" : "=r"(u) : "f"(x));
    return __uint_as_float(u);
}

DI void mma_tf32(float c[4], uint32_t a0, uint32_t a1, uint32_t a2, uint32_t a3,
                 uint32_t b0, uint32_t b1) {
    asm volatile(
        "mma.sync.aligned.m16n8k8.row.col.f32.tf32.tf32.f32 "
        "{%0,%1,%2,%3}, {%4,%5,%6,%7}, {%8,%9}, {%0,%1,%2,%3};"
        : "+f"(c[0]), "+f"(c[1]), "+f"(c[2]), "+f"(c[3])
        : "r"(a0), "r"(a1), "r"(a2), "r"(a3), "r"(b0), "r"(b1));
}

// ---------------- generic batched TF32 GEMM ----------------
// C[z] = alpha * A[z] @ B[z] (+ bias over N).  BT=false: B is [K,N] row-major.
// BT=true: B is [N,K] row-major (i.e. compute A @ B^T).
// z = z1*Z2 + z2; per-operand offsets are z1*s?1 + z2*s?2.
// All of M, N multiples of 128 and K multiples of 16 (true for every call here).
template <bool BT>
__global__ __launch_bounds__(256) void gemm_tf32_k(
    const float* __restrict__ Ag, const float* __restrict__ Bg,
    float* __restrict__ Cg, const float* __restrict__ bias,
    int M, int N, int K, int lda, int ldb, int ldc,
    long long sA1, long long sA2, long long sB1, long long sB2,
    long long sC1, long long sC2, int Z2, int sbias2, float alpha)
{
    const int z = blockIdx.z, z1 = z / Z2, z2 = z % Z2;
    const float* A  = Ag + z1 * sA1 + z2 * sA2;
    const float* Bp = Bg + z1 * sB1 + z2 * sB2;
    float* C        = Cg + z1 * sC1 + z2 * sC2;
    const float* bp = bias ? bias + (long long)z2 * sbias2 : nullptr;

    const int bm = blockIdx.y * 128, bn = blockIdx.x * 128;

    __shared__ __align__(16) float As[2][16][136];
    __shared__ __align__(16) float Bs[2][16][136];

    const int tid = threadIdx.x, lane = tid & 31, warp = tid >> 5;
    const int wm = (warp & 1) * 64, wn = (warp >> 1) * 32;
    const int g = lane >> 2, q = lane & 3;

    float acc[4][4][4];
#pragma unroll
    for (int i = 0; i < 4; i++)
#pragma unroll
        for (int j = 0; j < 4; j++)
#pragma unroll
            for (int k = 0; k < 4; k++) acc[i][j][k] = 0.f;

    // loader index precompute (512 float4 per tile, 2 per thread)
    int aRow[2], aKc[2], bRow[2], bNc[2];
#pragma unroll
    for (int i = 0; i < 2; i++) {
        int id = tid + i * 256;
        aRow[i] = id >> 2;
        aKc[i]  = (id & 3) * 4;
        if (BT) { bRow[i] = id >> 2;  bNc[i] = (id & 3) * 4;  }   // bRow = n, bNc = k
        else    { bRow[i] = id >> 5;  bNc[i] = (id & 31) * 4; }   // bRow = k, bNc = n
    }

    float4 ra[2], rb[2];
    auto ldg = [&](int kt) {
#pragma unroll
        for (int i = 0; i < 2; i++) {
            ra[i] = *(const float4*)(A + (long long)(bm + aRow[i]) * lda + kt * 16 + aKc[i]);
            if (BT)
                rb[i] = *(const float4*)(Bp + (long long)(bn + bRow[i]) * ldb + kt * 16 + bNc[i]);
            else
                rb[i] = *(const float4*)(Bp + (long long)(kt * 16 + bRow[i]) * ldb + bn + bNc[i]);
        }
    };
    auto sts = [&](int buf) {
#pragma unroll
        for (int i = 0; i < 2; i++) {
            As[buf][aKc[i] + 0][aRow[i]] = tf32r(ra[i].x);
            As[buf][aKc[i] + 1][aRow[i]] = tf32r(ra[i].y);
            As[buf][aKc[i] + 2][aRow[i]] = tf32r(ra[i].z);
            As[buf][aKc[i] + 3][aRow[i]] = tf32r(ra[i].w);
            if (BT) {
                Bs[buf][bNc[i] + 0][bRow[i]] = tf32r(rb[i].x);
                Bs[buf][bNc[i] + 1][bRow[i]] = tf32r(rb[i].y);
                Bs[buf][bNc[i] + 2][bRow[i]] = tf32r(rb[i].z);
                Bs[buf][bNc[i] + 3][bRow[i]] = tf32r(rb[i].w);
            } else {
                float4 t = make_float4(tf32r(rb[i].x), tf32r(rb[i].y),
                                       tf32r(rb[i].z), tf32r(rb[i].w));
                *(float4*)&Bs[buf][bRow[i]][bNc[i]] = t;
            }
        }
    };

    const int kt_n = K >> 4;
    ldg(0);
    sts(0);
    __syncthreads();
    int cur = 0;

    for (int kt = 0; kt < kt_n; kt++) {
        if (kt + 1 < kt_n) ldg(kt + 1);
#pragma unroll
        for (int ks = 0; ks < 16; ks += 8) {
            uint32_t af[4][4], bf[4][2];
#pragma unroll
            for (int mt = 0; mt < 4; mt++) {
                int mb = wm + mt * 16;
                af[mt][0] = __float_as_uint(As[cur][ks + q][mb + g]);
                af[mt][1] = __float_as_uint(As[cur][ks + q][mb + g + 8]);
                af[mt][2] = __float_as_uint(As[cur][ks + q + 4][mb + g]);
                af[mt][3] = __float_as_uint(As[cur][ks + q + 4][mb + g + 8]);
            }
#pragma unroll
            for (int nt = 0; nt < 4; nt++) {
                int nb = wn + nt * 8;
                bf[nt][0] = __float_as_uint(Bs[cur][ks + q][nb + g]);
                bf[nt][1] = __float_as_uint(Bs[cur][ks + q + 4][nb + g]);
            }
#pragma unroll
            for (int mt = 0; mt < 4; mt++)
#pragma unroll
                for (int nt = 0; nt < 4; nt++)
                    mma_tf32(acc[mt][nt], af[mt][0], af[mt][1], af[mt][2], af[mt][3],
                             bf[nt][0], bf[nt][1]);
        }
        if (kt + 1 < kt_n) sts(cur ^ 1);
        __syncthreads();
        cur ^= 1;
    }

    // epilogue
#pragma unroll
    for (int mt = 0; mt < 4; mt++) {
#pragma unroll
        for (int nt = 0; nt < 4; nt++) {
            int r = bm + wm + mt * 16 + g;
            int c = bn + wn + nt * 8 + q * 2;
            float b0v = bp ? bp[c] : 0.f;
            float b1v = bp ? bp[c + 1] : 0.f;
            float2 v0 = make_float2(alpha * acc[mt][nt][0] + b0v,
                                    alpha * acc[mt][nt][1] + b1v);
            float2 v1 = make_float2(alpha * acc[mt][nt][2] + b0v,
                                    alpha * acc[mt][nt][3] + b1v);
            *(float2*)(C + (long long)r * ldc + c)       = v0;
            *(float2*)(C + (long long)(r + 8) * ldc + c) = v1;
        }
    }
}

// ---------------- folded bias: cvec = bo + bv_flat @ Wo ----------------
__global__ void cvec_partial_k(const float* __restrict__ bv, const float* __restrict__ Wo) {
    int j = blockIdx.x * 256 + threadIdx.x;   // grid.x = 4
    int r0 = blockIdx.y * 256;                // grid.y = 32
    float acc = 0.f;
    for (int r = r0; r < r0 + 256; r++) acc += bv[r] * Wo[(size_t)r * D_ + j];
    g_cpart[blockIdx.y * D_ + j] = acc;
}
__global__ void cvec_final_k(const float* __restrict__ bo) {
    int j = blockIdx.x * 256 + threadIdx.x;   // grid.x = 4
    float acc = bo[j];
    for (int r = 0; r < 32; r++) acc += g_cpart[r * D_ + j];
    g_cvec[j] = acc;
}

// ---------------- row softmax on g_P (rows of length 2048) ----------------
__global__ __launch_bounds__(256) void softmax_k() {
    float* row = g_P + (size_t)blockIdx.x * S_;
    int tid = threadIdx.x;
    float v[8];
    float mx = -1e30f;
#pragma unroll
    for (int i = 0; i < 8; i++) {
        v[i] = row[tid + i * 256];
        mx = fmaxf(mx, v[i]);
    }
#pragma unroll
    for (int o = 16; o > 0; o >>= 1) mx = fmaxf(mx, __shfl_xor_sync(0xffffffffu, mx, o));
    __shared__ float red[8];
    if ((tid & 31) == 0) red[tid >> 5] = mx;
    __syncthreads();
    mx = red[0];
#pragma unroll
    for (int w = 1; w < 8; w++) mx = fmaxf(mx, red[w]);

    float s = 0.f;
#pragma unroll
    for (int i = 0; i < 8; i++) {
        v[i] = exp2f((v[i] - mx) * 1.4426950408889634f);
        s += v[i];
    }
#pragma unroll
    for (int o = 16; o > 0; o >>= 1) s += __shfl_xor_sync(0xffffffffu, s, o);
    __syncthreads();
    if ((tid & 31) == 0) red[tid >> 5] = s;
    __syncthreads();
    s = 0.f;
#pragma unroll
    for (int w = 0; w < 8; w++) s += red[w];
    float inv = 1.f / s;
#pragma unroll
    for (int i = 0; i < 8; i++) row[tid + i * 256] = v[i] * inv;
}

// ---------------- sum over heads + folded bias ----------------
__global__ __launch_bounds__(256) void final_reduce_k(float* __restrict__ out) {
    int rowid = blockIdx.x;               // b*2048 + s, grid.x = 8192
    int b = rowid >> 11, s = rowid & 2047;
#pragma unroll
    for (int jj = 0; jj < 4; jj++) {
        int j = threadIdx.x + jj * 256;
        float acc = g_cvec[j];
#pragma unroll
        for (int h = 0; h < 8; h++)
            acc += g_O[(((size_t)(b * 8 + h) * S_) + s) * D_ + j];
        out[(size_t)rowid * D_ + j] = acc;
    }
}

// ---------------- launch ----------------
extern "C" void kernel_launch(void* const* d_in, const int* in_sizes, int n_in,
                              void* d_out, int out_size) {
    const float* z  = (const float*)d_in[0];
    const float* y  = (const float*)d_in[1];
    const float* Wq = (const float*)d_in[2];
    const float* bq = (const float*)d_in[3];
    const float* Wk = (const float*)d_in[4];
    const float* bk = (const float*)d_in[5];
    const float* Wv = (const float*)d_in[6];
    const float* bv = (const float*)d_in[7];
    const float* Wo = (const float*)d_in[8];
    const float* bo = (const float*)d_in[9];
    float* out = (float*)d_out;

    float *pM, *pQ, *pK, *pU, *pP, *pO;
    cudaGetSymbolAddress((void**)&pM, g_M);
    cudaGetSymbolAddress((void**)&pQ, g_Q);
    cudaGetSymbolAddress((void**)&pK, g_Kb);
    cudaGetSymbolAddress((void**)&pU, g_U);
    cudaGetSymbolAddress((void**)&pP, g_P);
    cudaGetSymbolAddress((void**)&pO, g_O);

    // 1) M_h = Wv_h @ Wo_h                    [8] x (1024x1024x1024)
    gemm_tf32_k<false><<<dim3(8, 8, 8), 256>>>(
        Wv, Wo, pM, nullptr,
        1024, 1024, 1024, 1024, 1024, 1024,
        1024LL * 1024, 0, 1024LL * 1024, 0, 1024LL * 1024, 0, 1, 0, 1.f);

    // 2) folded bias vector
    cvec_partial_k<<<dim3(4, 32), 256>>>(bv, Wo);
    cvec_final_k<<<4, 256>>>(bo);

    // 3) Q = y @ Wq_h + bq                    [4*8] x (2048x128x1024)
    gemm_tf32_k<false><<<dim3(1, 16, 32), 256>>>(
        y, Wq, pQ, bq,
        2048, 128, 1024, 1024, 128, 128,
        2048LL * 1024, 0, 0, 1024LL * 128, 8LL * 2048 * 128, 2048LL * 128, 8, 128, 1.f);

    // 4) K = z @ Wk_h + bk
    gemm_tf32_k<false><<<dim3(1, 16, 32), 256>>>(
        z, Wk, pK, bk,
        2048, 128, 1024, 1024, 128, 128,
        2048LL * 1024, 0, 0, 1024LL * 128, 8LL * 2048 * 128, 2048LL * 128, 8, 128, 1.f);

    // 5) U = z @ M_h                           [4*8] x (2048x1024x1024)
    gemm_tf32_k<false><<<dim3(8, 16, 32), 256>>>(
        z, pM, pU, nullptr,
        2048, 1024, 1024, 1024, 1024, 1024,
        2048LL * 1024, 0, 0, 1024LL * 1024, 8LL * 2048 * 1024, 2048LL * 1024, 8, 0, 1.f);

    // 6) scores = (Q @ K^T) / sqrt(128)        [4*8] x (2048x2048x128)
    gemm_tf32_k<true><<<dim3(16, 16, 32), 256>>>(
        pQ, pK, pP, nullptr,
        2048, 2048, 128, 128, 128, 2048,
        8LL * 2048 * 128, 2048LL * 128, 8LL * 2048 * 128, 2048LL * 128,
        8LL * 2048 * 2048, 2048LL * 2048, 8, 0, 0.08838834764831845f);

    // 7) softmax rows
    softmax_k<<<B_ * H_ * S_, 256>>>();

    // 8) O_h = P @ U                            [4*8] x (2048x1024x2048)
    gemm_tf32_k<false><<<dim3(8, 16, 32), 256>>>(
        pP, pU, pO, nullptr,
        2048, 1024, 2048, 2048, 1024, 1024,
        8LL * 2048 * 2048, 2048LL * 2048, 8LL * 2048 * 1024, 2048LL * 1024,
        8LL * 2048 * 1024, 2048LL * 1024, 8, 0, 1.f);

    // 9) out = sum_h O_h + cvec
    final_reduce_k<<<B_ * S_, 256>>>(out);
}

// round 3
// speedup vs baseline: 1.0278x; 1.0278x over previous
#include <cuda_runtime.h>
#include <cstdint>

#define DI __device__ __forceinline__

static constexpr int B_ = 4, H_ = 8, S_ = 2048, D_ = 1024, KQ_ = 128;

// ---------------- scratch (device globals; no allocations allowed) ----------------
__device__ float g_M[(size_t)H_ * D_ * D_];        //  32 MB  M_h = Wv_h @ Wo_h
__device__ float g_cvec[D_];                       //  folded bias bo + bv@Wo
__device__ float g_cpart[32 * D_];
__device__ float g_Q[(size_t)B_ * H_ * S_ * KQ_];  //  32 MB
__device__ float g_Kb[(size_t)B_ * H_ * S_ * KQ_]; //  32 MB
__device__ float g_U[(size_t)B_ * H_ * S_ * D_];   // 256 MB  U = z @ M_h
__device__ float g_P[(size_t)B_ * H_ * S_ * S_];   // 512 MB  scores / attn

// ---------------- helpers ----------------
DI uint32_t smem_u32(const void* p) {
    uint32_t a;
    asm("{ .reg .u64 t; cvta.to.shared.u64 t, %1; cvt.u32.u64 %0, t; }" : "=r"(a) : "l"(p));
    return a;
}
DI float tf32r(float x) {
    uint32_t u;
    asm("cvt.rna.tf32.f32 %0, %1;" : "=r"(u) : "f"(x));
    return __uint_as_float(u);
}
DI void mma_tf32(float c[4], uint32_t a0, uint32_t a1, uint32_t a2, uint32_t a3,
                 uint32_t b0, uint32_t b1) {
    asm volatile(
        "mma.sync.aligned.m16n8k8.row.col.f32.tf32.tf32.f32 "
        "{%0,%1,%2,%3}, {%4,%5,%6,%7}, {%8,%9}, {%0,%1,%2,%3};"
        : "+f"(c[0]), "+f"(c[1]), "+f"(c[2]), "+f"(c[3])
        : "r"(a0), "r"(a1), "r"(a2), "r"(a3), "r"(b0), "r"(b1));
}
DI void ldsm4(uint32_t r[4], uint32_t a) {
    asm volatile("ldmatrix.sync.aligned.m8n8.x4.shared.b16 {%0,%1,%2,%3}, [%4];"
                 : "=r"(r[0]), "=r"(r[1]), "=r"(r[2]), "=r"(r[3]) : "r"(a));
}
DI void sts4(uint32_t a, float x, float y, float z, float w) {
    asm volatile("st.shared.v4.f32 [%0], {%1,%2,%3,%4};"
                 :: "r"(a), "f"(x), "f"(y), "f"(z), "f"(w) : "memory");
}

// ======================= ldmatrix + mma.sync tf32 batched GEMM =======================
// C = alpha * A @ op(B) + bias.  CTA tile 128x128, 256 threads, warp tile 64x32.
// K consumed in chunks of 16 floats; operand tiles stored [row][16] with XOR swizzle.
// BMODE=0: B gmem [K,N] row-major (NN).  BMODE=1: B gmem [N,K] row-major (NT).
// z = blockIdx.z; z1=z/Z2, z2=z%Z2; operand base offset z1*s?1 + z2*s?2.
// head-fused K: chunk c -> h = c>>hshift (extra offset h*s?h), k-offset (c&hmask)*16.
template <int BMODE>
__global__ __launch_bounds__(256) void mma_gemm(
    const float* __restrict__ Ag, const float* __restrict__ Bg,
    float* __restrict__ Cg, const float* __restrict__ bias,
    int kchunks, int lda, int ldb, int ldc,
    long long sA1, long long sA2, long long sB1, long long sB2,
    long long sC1, long long sC2, int Z2, int sbias2, float alpha,
    int hshift, long long sAh, long long sBh)
{
    __shared__ __align__(128) float sAs[2][2048];
    __shared__ __align__(128) float sBs[2][2048];

    const int tid = threadIdx.x, lane = tid & 31, wid = tid >> 5;
    const int wm = (wid & 1) * 64, wn = (wid >> 1) * 32;
    const int g = lane >> 2, q = lane & 3;

    const int z = blockIdx.z, z1 = z / Z2, z2 = z % Z2;
    const float* A = Ag + z1 * sA1 + z2 * sA2;
    const float* Bp = Bg + z1 * sB1 + z2 * sB2;
    float* C = Cg + z1 * sC1 + z2 * sC2;
    const int bm = blockIdx.y * 128, bn = blockIdx.x * 128;

    // ---- loader geometry: 2 float4 per thread per operand tile ----
    long long aoff[2], boffT[2];
    uint32_t adst[2];
#pragma unroll
    for (int i = 0; i < 2; i++) {
        int id = i * 256 + tid;
        int row = id >> 2, kb = id & 3;
        aoff[i]  = (long long)(bm + row) * lda + kb * 4;
        boffT[i] = (long long)(bn + row) * ldb + kb * 4;
        adst[i]  = (uint32_t)(row * 64 + ((kb ^ ((row >> 1) & 3)) << 4));
    }
    // NN B loader: thread -> column n = tid&127, k-half = tid>>7
    const int nn_n = tid & 127, nn_kh = tid >> 7;
    uint32_t bdstN[2];
#pragma unroll
    for (int i = 0; i < 2; i++) {
        int k0 = nn_kh * 8 + i * 4;
        bdstN[i] = (uint32_t)(nn_n * 64 + (((k0 >> 2) ^ ((nn_n >> 1) & 3)) << 4));
    }

    const uint32_t sAb = smem_u32(&sAs[0][0]);
    const uint32_t sBb = smem_u32(&sBs[0][0]);

    // ---- ldmatrix per-lane addresses ----
    const int l7 = lane & 7;
    const uint32_t sw = (uint32_t)((l7 >> 1) & 3);
    const uint32_t rowAb = (uint32_t)(wm + l7 + ((lane >> 3) & 1) * 8) * 64;
    const uint32_t kbA = (uint32_t)(lane >> 4);
    const uint32_t rowBb = (uint32_t)(wn + l7 + (lane >> 4) * 8) * 64;
    const uint32_t kbB = (uint32_t)((lane >> 3) & 1);

    float acc[4][4][4];
#pragma unroll
    for (int i = 0; i < 4; i++)
#pragma unroll
        for (int j = 0; j < 4; j++)
#pragma unroll
            for (int k = 0; k < 4; k++) acc[i][j][k] = 0.f;

    float4 va[2], vbt[2];
    float vbn[2][4];
    const int hmask = (hshift < 30) ? ((1 << hshift) - 1) : 0x3FFFFFFF;

    auto ldg = [&](int c) {
        const long long hA = (long long)(c >> hshift) * sAh;
        const long long hB = (long long)(c >> hshift) * sBh;
        const int koff = (c & hmask) * 16;
        const float* Ac = A + hA + koff;
#pragma unroll
        for (int i = 0; i < 2; i++) va[i] = *(const float4*)(Ac + aoff[i]);
        if (BMODE == 1) {
            const float* Bc = Bp + hB + koff;
#pragma unroll
            for (int i = 0; i < 2; i++) vbt[i] = *(const float4*)(Bc + boffT[i]);
        } else {
            const float* Bc = Bp + hB + (long long)koff * ldb + bn + nn_n;
#pragma unroll
            for (int i = 0; i < 2; i++) {
                int k0 = nn_kh * 8 + i * 4;
#pragma unroll
                for (int t = 0; t < 4; t++) vbn[i][t] = Bc[(long long)(k0 + t) * ldb];
            }
        }
    };
    auto sts = [&](int st) {
        const uint32_t a0 = sAb + st * 8192, b0 = sBb + st * 8192;
#pragma unroll
        for (int i = 0; i < 2; i++)
            sts4(a0 + adst[i], tf32r(va[i].x), tf32r(va[i].y), tf32r(va[i].z), tf32r(va[i].w));
        if (BMODE == 1) {
#pragma unroll
            for (int i = 0; i < 2; i++)
                sts4(b0 + adst[i], tf32r(vbt[i].x), tf32r(vbt[i].y), tf32r(vbt[i].z), tf32r(vbt[i].w));
        } else {
#pragma unroll
            for (int i = 0; i < 2; i++)
                sts4(b0 + bdstN[i], tf32r(vbn[i][0]), tf32r(vbn[i][1]),
                     tf32r(vbn[i][2]), tf32r(vbn[i][3]));
        }
    };

    ldg(0);
    sts(0);

    for (int c = 0; c < kchunks; c++) {
        __syncthreads();
        const int st = c & 1;
        if (c + 1 < kchunks) ldg(c + 1);
        const uint32_t aB = sAb + st * 8192, bB = sBb + st * 8192;
#pragma unroll
        for (int ks2 = 0; ks2 < 2; ks2++) {
            uint32_t af[4][4], bf[4][2];
#pragma unroll
            for (int mt = 0; mt < 4; mt++)
                ldsm4(af[mt], aB + rowAb + mt * 1024 + (((ks2 * 2 + kbA) ^ sw) << 4));
#pragma unroll
            for (int ntp = 0; ntp < 2; ntp++) {
                uint32_t t4[4];
                ldsm4(t4, bB + rowBb + ntp * 1024 + (((ks2 * 2 + kbB) ^ sw) << 4));
                bf[2 * ntp][0] = t4[0];
                bf[2 * ntp][1] = t4[1];
                bf[2 * ntp + 1][0] = t4[2];
                bf[2 * ntp + 1][1] = t4[3];
            }
#pragma unroll
            for (int mt = 0; mt < 4; mt++)
#pragma unroll
                for (int nt = 0; nt < 4; nt++)
                    mma_tf32(acc[mt][nt], af[mt][0], af[mt][1], af[mt][2], af[mt][3],
                             bf[nt][0], bf[nt][1]);
        }
        if (c + 1 < kchunks) sts(st ^ 1);
    }

    // ---- epilogue: direct STG float2 ----
    const float* bp = bias ? bias + (long long)z2 * sbias2 : nullptr;
#pragma unroll
    for (int mt = 0; mt < 4; mt++) {
#pragma unroll
        for (int nt = 0; nt < 4; nt++) {
            int r = bm + wm + mt * 16 + g;
            int cc = bn + wn + nt * 8 + q * 2;
            float b0v = bp ? bp[cc] : 0.f;
            float b1v = bp ? bp[cc + 1] : 0.f;
            float2 v0 = make_float2(alpha * acc[mt][nt][0] + b0v,
                                    alpha * acc[mt][nt][1] + b1v);
            float2 v1 = make_float2(alpha * acc[mt][nt][2] + b0v,
                                    alpha * acc[mt][nt][3] + b1v);
            *(float2*)(C + (long long)r * ldc + cc)       = v0;
            *(float2*)(C + (long long)(r + 8) * ldc + cc) = v1;
        }
    }
}

// ---------------- folded bias: cvec = bo + bv_flat @ Wo ----------------
__global__ void cvec_partial_k(const float* __restrict__ bv, const float* __restrict__ Wo) {
    int j = blockIdx.x * 256 + threadIdx.x;
    int r0 = blockIdx.y * 256;
    float acc = 0.f;
    for (int r = r0; r < r0 + 256; r++) acc += bv[r] * Wo[(size_t)r * D_ + j];
    g_cpart[blockIdx.y * D_ + j] = acc;
}
__global__ void cvec_final_k(const float* __restrict__ bo) {
    int j = blockIdx.x * 256 + threadIdx.x;
    float acc = bo[j];
    for (int r = 0; r < 32; r++) acc += g_cpart[r * D_ + j];
    g_cvec[j] = acc;
}

// ---------------- row softmax on g_P (rows of length 2048) ----------------
__global__ __launch_bounds__(256) void softmax_k() {
    float* row = g_P + (size_t)blockIdx.x * S_;
    int tid = threadIdx.x;
    float v[8];
    float mx = -1e30f;
#pragma unroll
    for (int i = 0; i < 8; i++) {
        v[i] = row[tid + i * 256];
        mx = fmaxf(mx, v[i]);
    }
#pragma unroll
    for (int o = 16; o > 0; o >>= 1) mx = fmaxf(mx, __shfl_xor_sync(0xffffffffu, mx, o));
    __shared__ float red[8];
    if ((tid & 31) == 0) red[tid >> 5] = mx;
    __syncthreads();
    mx = red[0];
#pragma unroll
    for (int w = 1; w < 8; w++) mx = fmaxf(mx, red[w]);

    float s = 0.f;
#pragma unroll
    for (int i = 0; i < 8; i++) {
        v[i] = exp2f((v[i] - mx) * 1.4426950408889634f);
        s += v[i];
    }
#pragma unroll
    for (int o = 16; o > 0; o >>= 1) s += __shfl_xor_sync(0xffffffffu, s, o);
    __syncthreads();
    if ((tid & 31) == 0) red[tid >> 5] = s;
    __syncthreads();
    s = 0.f;
#pragma unroll
    for (int w = 0; w < 8; w++) s += red[w];
    float inv = 1.f / s;
#pragma unroll
    for (int i = 0; i < 8; i++) row[tid + i * 256] = v[i] * inv;
}

// ---------------- launch ----------------
extern "C" void kernel_launch(void* const* d_in, const int* in_sizes, int n_in,
                              void* d_out, int out_size) {
    const float* z  = (const float*)d_in[0];
    const float* y  = (const float*)d_in[1];
    const float* Wq = (const float*)d_in[2];
    const float* bq = (const float*)d_in[3];
    const float* Wk = (const float*)d_in[4];
    const float* bk = (const float*)d_in[5];
    const float* Wv = (const float*)d_in[6];
    const float* bv = (const float*)d_in[7];
    const float* Wo = (const float*)d_in[8];
    const float* bo = (const float*)d_in[9];
    float* out = (float*)d_out;

    float *pM, *pQ, *pK, *pU, *pP, *pc;
    cudaGetSymbolAddress((void**)&pM, g_M);
    cudaGetSymbolAddress((void**)&pQ, g_Q);
    cudaGetSymbolAddress((void**)&pK, g_Kb);
    cudaGetSymbolAddress((void**)&pU, g_U);
    cudaGetSymbolAddress((void**)&pP, g_P);
    cudaGetSymbolAddress((void**)&pc, g_cvec);

    // 1) M_h = Wv_h @ Wo_h                        [8] x (1024,1024,1024)
    mma_gemm<0><<<dim3(8, 8, 8), 256>>>(
        Wv, Wo, pM, nullptr, 64, 1024, 1024, 1024,
        0, 1024LL * 1024, 0, 1024LL * 1024, 0, 1024LL * 1024,
        8, 0, 1.f, 30, 0, 0);

    // 2) folded bias vector
    cvec_partial_k<<<dim3(4, 32), 256>>>(bv, Wo);
    cvec_final_k<<<4, 256>>>(bo);

    // 3) Q = y @ Wq_h + bq                        [b,h] x (2048,128,1024)
    mma_gemm<0><<<dim3(1, 16, 32), 256>>>(
        y, Wq, pQ, bq, 64, 1024, 128, 128,
        2048LL * 1024, 0, 0, 1024LL * 128, 8LL * 2048 * 128, 2048LL * 128,
        8, 128, 1.f, 30, 0, 0);

    // 4) K = z @ Wk_h + bk
    mma_gemm<0><<<dim3(1, 16, 32), 256>>>(
        z, Wk, pK, bk, 64, 1024, 128, 128,
        2048LL * 1024, 0, 0, 1024LL * 128, 8LL * 2048 * 128, 2048LL * 128,
        8, 128, 1.f, 30, 0, 0);

    // 5) U = z @ M_h                              [b,h] x (2048,1024,1024)
    mma_gemm<0><<<dim3(8, 16, 32), 256>>>(
        z, pM, pU, nullptr, 64, 1024, 1024, 1024,
        2048LL * 1024, 0, 0, 1024LL * 1024, 8LL * 2048 * 1024, 2048LL * 1024,
        8, 0, 1.f, 30, 0, 0);

    // 6) scores = (Q @ K^T) * 1/sqrt(128)         [b,h] x (2048,2048,128)  NT
    mma_gemm<1><<<dim3(16, 16, 32), 256>>>(
        pQ, pK, pP, nullptr, 8, 128, 128, 2048,
        8LL * 2048 * 128, 2048LL * 128, 8LL * 2048 * 128, 2048LL * 128,
        8LL * 2048 * 2048, 2048LL * 2048, 8, 0, 0.08838834764831845f, 30, 0, 0);

    // 7) softmax rows
    softmax_k<<<B_ * H_ * S_, 256>>>();

    // 8) out = sum_h P_h @ U_h + cvec             [b] x (2048,1024, K=8*2048) head-fused
    mma_gemm<0><<<dim3(8, 16, 4), 256>>>(
        pP, pU, out, pc, 1024, 2048, 1024, 1024,
        0, 8LL * 2048 * 2048, 0, 8LL * 2048 * 1024, 0, 2048LL * 1024,
        4, 0, 1.f, 7, 2048LL * 2048, 2048LL * 1024);
}

// round 5
// speedup vs baseline: 1.3468x; 1.3103x over previous
#include <cuda_runtime.h>
#include <cuda_fp16.h>
#include <cstdint>

#define DI __device__ __forceinline__

static constexpr int B_ = 4, H_ = 8, S_ = 2048, D_ = 1024, KQ_ = 128;

// ---------------- scratch (device globals; no allocations allowed) ----------------
__device__ float g_M[(size_t)H_ * D_ * D_];        //  32 MB  M_h = Wv_h @ Wo_h
__device__ float g_cvec[D_];                       //  folded bias bo + bv@Wo
__device__ float g_cpart[32 * D_];
__device__ float g_Q[(size_t)B_ * H_ * S_ * KQ_];  //  32 MB
__device__ float g_Kb[(size_t)B_ * H_ * S_ * KQ_]; //  32 MB
__device__ float g_U[(size_t)B_ * H_ * S_ * D_];   // 256 MB  U = z @ M_h
__device__ float g_P[(size_t)B_ * H_ * S_ * S_];   // 512 MB  scores / attn

// ---------------- helpers ----------------
DI uint32_t smem_u32(const void* p) {
    uint32_t a;
    asm("{ .reg .u64 t; cvta.to.shared.u64 t, %1; cvt.u32.u64 %0, t; }" : "=r"(a) : "l"(p));
    return a;
}
DI uint32_t pack2(float a, float b) {
    __half2 h = __floats2half2_rn(a, b);   // .x (low) = a
    return *reinterpret_cast<uint32_t*>(&h);
}
DI void mma_f16(float c[4], uint32_t a0, uint32_t a1, uint32_t a2, uint32_t a3,
                uint32_t b0, uint32_t b1) {
    asm volatile(
        "mma.sync.aligned.m16n8k16.row.col.f32.f16.f16.f32 "
        "{%0,%1,%2,%3}, {%4,%5,%6,%7}, {%8,%9}, {%0,%1,%2,%3};"
        : "+f"(c[0]), "+f"(c[1]), "+f"(c[2]), "+f"(c[3])
        : "r"(a0), "r"(a1), "r"(a2), "r"(a3), "r"(b0), "r"(b1));
}
DI void ldsm4(uint32_t r[4], uint32_t a) {
    asm volatile("ldmatrix.sync.aligned.m8n8.x4.shared.b16 {%0,%1,%2,%3}, [%4];"
                 : "=r"(r[0]), "=r"(r[1]), "=r"(r[2]), "=r"(r[3]) : "r"(a));
}
DI void sts4(uint32_t a, uint32_t x, uint32_t y, uint32_t z, uint32_t w) {
    asm volatile("st.shared.v4.b32 [%0], {%1,%2,%3,%4};"
                 :: "r"(a), "r"(x), "r"(y), "r"(z), "r"(w) : "memory");
}

// ======================= fp16 ldmatrix + mma.sync batched GEMM =======================
// C = alpha * A @ op(B) + bias.  CTA 128x128, 256 threads, warp tile 64x32.
// K consumed in chunks of 32 floats. SMEM tiles: 128 rows x 32 halves (64B/row),
// 16B chunk (r,c in 0..3) stored at p = r*4 + (c ^ ((r>>1)&3))  (conflict-free
// for v4 STS and all ldmatrix.x4 phases).
// BMODE=0: B gmem [K,N] row-major (NN, transposed to n-major at STS).
// BMODE=1: B gmem [N,K] row-major (NT, direct).
// z = blockIdx.z; z1=z/Z2, z2=z%Z2; base offset z1*s?1 + z2*s?2.
// head-fused K: chunk c -> h = c>>hshift (extra offset h*s?h), k-off (c&hmask)*32.
template <int BMODE>
__global__ __launch_bounds__(256, 2) void mma_gemm(
    const float* __restrict__ Ag, const float* __restrict__ Bg,
    float* __restrict__ Cg, const float* __restrict__ bias,
    int kchunks, int lda, int ldb, int ldc,
    long long sA1, long long sA2, long long sB1, long long sB2,
    long long sC1, long long sC2, int Z2, int sbias2, float alpha,
    int hshift, long long sAh, long long sBh)
{
    __shared__ __align__(128) uint32_t sAs[2][2048];   // 2 stages x 8KB
    __shared__ __align__(128) uint32_t sBs[2][2048];

    const int tid = threadIdx.x, lane = tid & 31, wid = tid >> 5;
    const int wm = (wid & 1) * 64, wn = (wid >> 1) * 32;
    const int g = lane >> 2, q = lane & 3;

    const int z = blockIdx.z, z1 = z / Z2, z2 = z % Z2;
    const float* A = Ag + z1 * sA1 + z2 * sA2;
    const float* Bp = Bg + z1 * sB1 + z2 * sB2;
    float* C = Cg + z1 * sC1 + z2 * sC2;
    const int bm = blockIdx.y * 128, bn = blockIdx.x * 128;

    // ---- loader geometry: 2 chunks (16B smem each / 32B gmem) per thread per tile ----
    int lr[2], lc[2];
    uint32_t dst[2];
    long long aoff[2], boffT[2];
#pragma unroll
    for (int i = 0; i < 2; i++) {
        int qid = tid + i * 256;
        lr[i] = qid >> 2;           // row (A) / n (B)
        lc[i] = qid & 3;            // 8-half chunk within 32
        dst[i] = (uint32_t)((lr[i] * 4 + (lc[i] ^ ((lr[i] >> 1) & 3))) << 4);
        aoff[i]  = (long long)(bm + lr[i]) * lda + lc[i] * 8;
        boffT[i] = (long long)(bn + lr[i]) * ldb + lc[i] * 8;
    }

    const uint32_t sAb = smem_u32(&sAs[0][0]);
    const uint32_t sBb = smem_u32(&sBs[0][0]);

    // ---- ldmatrix per-lane geometry ----
    const int l15 = lane & 15, hs = lane >> 4;
    uint32_t arow[4], axor[4], brow[2], bxor[2];
#pragma unroll
    for (int mt = 0; mt < 4; mt++) {
        int rr = wm + mt * 16 + l15;
        arow[mt] = (uint32_t)(rr * 64);
        axor[mt] = (uint32_t)((rr >> 1) & 3);
    }
#pragma unroll
    for (int np = 0; np < 2; np++) {
        int nn = wn + np * 16 + l15;
        brow[np] = (uint32_t)(nn * 64);
        bxor[np] = (uint32_t)((nn >> 1) & 3);
    }

    float acc[4][4][4];
#pragma unroll
    for (int i = 0; i < 4; i++)
#pragma unroll
        for (int j = 0; j < 4; j++)
#pragma unroll
            for (int k = 0; k < 4; k++) acc[i][j][k] = 0.f;

    float va[2][8], vb[2][8];
    const int hmask = (hshift < 30) ? ((1 << hshift) - 1) : 0x3FFFFFFF;

    auto ldg = [&](int c) {
        const long long hA = (long long)(c >> hshift) * sAh;
        const long long hB = (long long)(c >> hshift) * sBh;
        const int koff = (c & hmask) * 32;
        const float* Ac = A + hA + koff;
#pragma unroll
        for (int i = 0; i < 2; i++) {
            float4 u = *(const float4*)(Ac + aoff[i]);
            float4 v = *(const float4*)(Ac + aoff[i] + 4);
            va[i][0] = u.x; va[i][1] = u.y; va[i][2] = u.z; va[i][3] = u.w;
            va[i][4] = v.x; va[i][5] = v.y; va[i][6] = v.z; va[i][7] = v.w;
        }
        if (BMODE == 1) {
            const float* Bc = Bp + hB + koff;
#pragma unroll
            for (int i = 0; i < 2; i++) {
                float4 u = *(const float4*)(Bc + boffT[i]);
                float4 v = *(const float4*)(Bc + boffT[i] + 4);
                vb[i][0] = u.x; vb[i][1] = u.y; vb[i][2] = u.z; vb[i][3] = u.w;
                vb[i][4] = v.x; vb[i][5] = v.y; vb[i][6] = v.z; vb[i][7] = v.w;
            }
        } else {
            const float* Bc = Bp + hB + (long long)koff * ldb + bn;
#pragma unroll
            for (int i = 0; i < 2; i++)
#pragma unroll
                for (int j = 0; j < 8; j++)
                    vb[i][j] = Bc[(long long)(lc[i] * 8 + j) * ldb + lr[i]];
        }
    };
    auto sts = [&](int st) {
        const uint32_t a0 = sAb + st * 8192, b0 = sBb + st * 8192;
#pragma unroll
        for (int i = 0; i < 2; i++) {
            sts4(a0 + dst[i], pack2(va[i][0], va[i][1]), pack2(va[i][2], va[i][3]),
                 pack2(va[i][4], va[i][5]), pack2(va[i][6], va[i][7]));
            sts4(b0 + dst[i], pack2(vb[i][0], vb[i][1]), pack2(vb[i][2], vb[i][3]),
                 pack2(vb[i][4], vb[i][5]), pack2(vb[i][6], vb[i][7]));
        }
    };

    ldg(0);
    sts(0);

    for (int c = 0; c < kchunks; c++) {
        __syncthreads();
        const int st = c & 1;
        if (c + 1 < kchunks) ldg(c + 1);
        const uint32_t aB = sAb + st * 8192, bB = sBb + st * 8192;
#pragma unroll
        for (int s = 0; s < 2; s++) {
            uint32_t af[4][4], bf[4][2];
            const uint32_t cc = (uint32_t)(2 * s + hs);
#pragma unroll
            for (int mt = 0; mt < 4; mt++)
                ldsm4(af[mt], aB + arow[mt] + ((cc ^ axor[mt]) << 4));
#pragma unroll
            for (int np = 0; np < 2; np++) {
                uint32_t t4[4];
                ldsm4(t4, bB + brow[np] + ((cc ^ bxor[np]) << 4));
                bf[2 * np][0] = t4[0];
                bf[2 * np][1] = t4[2];
                bf[2 * np + 1][0] = t4[1];
                bf[2 * np + 1][1] = t4[3];
            }
#pragma unroll
            for (int mt = 0; mt < 4; mt++)
#pragma unroll
                for (int nt = 0; nt < 4; nt++)
                    mma_f16(acc[mt][nt], af[mt][0], af[mt][1], af[mt][2], af[mt][3],
                            bf[nt][0], bf[nt][1]);
        }
        if (c + 1 < kchunks) sts(st ^ 1);
    }

    // ---- epilogue: direct STG float2 ----
    const float* bp = bias ? bias + (long long)z2 * sbias2 : nullptr;
#pragma unroll
    for (int mt = 0; mt < 4; mt++) {
#pragma unroll
        for (int nt = 0; nt < 4; nt++) {
            int r = bm + wm + mt * 16 + g;
            int cc = bn + wn + nt * 8 + q * 2;
            float b0v = bp ? bp[cc] : 0.f;
            float b1v = bp ? bp[cc + 1] : 0.f;
            float2 v0 = make_float2(alpha * acc[mt][nt][0] + b0v,
                                    alpha * acc[mt][nt][1] + b1v);
            float2 v1 = make_float2(alpha * acc[mt][nt][2] + b0v,
                                    alpha * acc[mt][nt][3] + b1v);
            *(float2*)(C + (long long)r * ldc + cc)       = v0;
            *(float2*)(C + (long long)(r + 8) * ldc + cc) = v1;
        }
    }
}

// ---------------- folded bias: cvec = bo + bv_flat @ Wo ----------------
__global__ void cvec_partial_k(const float* __restrict__ bv, const float* __restrict__ Wo) {
    int j = blockIdx.x * 256 + threadIdx.x;
    int r0 = blockIdx.y * 256;
    float acc = 0.f;
    for (int r = r0; r < r0 + 256; r++) acc += bv[r] * Wo[(size_t)r * D_ + j];
    g_cpart[blockIdx.y * D_ + j] = acc;
}
__global__ void cvec_final_k(const float* __restrict__ bo) {
    int j = blockIdx.x * 256 + threadIdx.x;
    float acc = bo[j];
    for (int r = 0; r < 32; r++) acc += g_cpart[r * D_ + j];
    g_cvec[j] = acc;
}

// ---------------- row softmax on g_P (rows of length 2048) ----------------
__global__ __launch_bounds__(256) void softmax_k() {
    float* row = g_P + (size_t)blockIdx.x * S_;
    int tid = threadIdx.x;
    float v[8];
    float mx = -1e30f;
#pragma unroll
    for (int i = 0; i < 8; i++) {
        v[i] = row[tid + i * 256];
        mx = fmaxf(mx, v[i]);
    }
#pragma unroll
    for (int o = 16; o > 0; o >>= 1) mx = fmaxf(mx, __shfl_xor_sync(0xffffffffu, mx, o));
    __shared__ float red[8];
    if ((tid & 31) == 0) red[tid >> 5] = mx;
    __syncthreads();
    mx = red[0];
#pragma unroll
    for (int w = 1; w < 8; w++) mx = fmaxf(mx, red[w]);

    float s = 0.f;
#pragma unroll
    for (int i = 0; i < 8; i++) {
        v[i] = exp2f((v[i] - mx) * 1.4426950408889634f);
        s += v[i];
    }
#pragma unroll
    for (int o = 16; o > 0; o >>= 1) s += __shfl_xor_sync(0xffffffffu, s, o);
    __syncthreads();
    if ((tid & 31) == 0) red[tid >> 5] = s;
    __syncthreads();
    s = 0.f;
#pragma unroll
    for (int w = 0; w < 8; w++) s += red[w];
    float inv = 1.f / s;
#pragma unroll
    for (int i = 0; i < 8; i++) row[tid + i * 256] = v[i] * inv;
}

// ---------------- launch ----------------
extern "C" void kernel_launch(void* const* d_in, const int* in_sizes, int n_in,
                              void* d_out, int out_size) {
    const float* z  = (const float*)d_in[0];
    const float* y  = (const float*)d_in[1];
    const float* Wq = (const float*)d_in[2];
    const float* bq = (const float*)d_in[3];
    const float* Wk = (const float*)d_in[4];
    const float* bk = (const float*)d_in[5];
    const float* Wv = (const float*)d_in[6];
    const float* bv = (const float*)d_in[7];
    const float* Wo = (const float*)d_in[8];
    const float* bo = (const float*)d_in[9];
    float* out = (float*)d_out;

    float *pM, *pQ, *pK, *pU, *pP, *pc;
    cudaGetSymbolAddress((void**)&pM, g_M);
    cudaGetSymbolAddress((void**)&pQ, g_Q);
    cudaGetSymbolAddress((void**)&pK, g_Kb);
    cudaGetSymbolAddress((void**)&pU, g_U);
    cudaGetSymbolAddress((void**)&pP, g_P);
    cudaGetSymbolAddress((void**)&pc, g_cvec);

    // 1) M_h = Wv_h @ Wo_h                        [8] x (1024,1024,1024)
    mma_gemm<0><<<dim3(8, 8, 8), 256>>>(
        Wv, Wo, pM, nullptr, 32, 1024, 1024, 1024,
        0, 1024LL * 1024, 0, 1024LL * 1024, 0, 1024LL * 1024,
        8, 0, 1.f, 30, 0, 0);

    // 2) folded bias vector
    cvec_partial_k<<<dim3(4, 32), 256>>>(bv, Wo);
    cvec_final_k<<<4, 256>>>(bo);

    // 3) Q = y @ Wq_h + bq                        [b,h] x (2048,128,1024)
    mma_gemm<0><<<dim3(1, 16, 32), 256>>>(
        y, Wq, pQ, bq, 32, 1024, 128, 128,
        2048LL * 1024, 0, 0, 1024LL * 128, 8LL * 2048 * 128, 2048LL * 128,
        8, 128, 1.f, 30, 0, 0);

    // 4) K = z @ Wk_h + bk
    mma_gemm<0><<<dim3(1, 16, 32), 256>>>(
        z, Wk, pK, bk, 32, 1024, 128, 128,
        2048LL * 1024, 0, 0, 1024LL * 128, 8LL * 2048 * 128, 2048LL * 128,
        8, 128, 1.f, 30, 0, 0);

    // 5) U = z @ M_h                              [b,h] x (2048,1024,1024)
    mma_gemm<0><<<dim3(8, 16, 32), 256>>>(
        z, pM, pU, nullptr, 32, 1024, 1024, 1024,
        2048LL * 1024, 0, 0, 1024LL * 1024, 8LL * 2048 * 1024, 2048LL * 1024,
        8, 0, 1.f, 30, 0, 0);

    // 6) scores = (Q @ K^T) * 1/sqrt(128)         [b,h] x (2048,2048,128)  NT
    mma_gemm<1><<<dim3(16, 16, 32), 256>>>(
        pQ, pK, pP, nullptr, 4, 128, 128, 2048,
        8LL * 2048 * 128, 2048LL * 128, 8LL * 2048 * 128, 2048LL * 128,
        8LL * 2048 * 2048, 2048LL * 2048, 8, 0, 0.08838834764831845f, 30, 0, 0);

    // 7) softmax rows
    softmax_k<<<B_ * H_ * S_, 256>>>();

    // 8) out = sum_h P_h @ U_h + cvec             [b] x (2048,1024, K=8*2048) head-fused
    //    chunk = 32 floats -> 64 chunks/head -> hshift = 6
    mma_gemm<0><<<dim3(8, 16, 4), 256>>>(
        pP, pU, out, pc, 512, 2048, 1024, 1024,
        0, 8LL * 2048 * 2048, 0, 8LL * 2048 * 1024, 0, 2048LL * 1024,
        4, 0, 1.f, 6, 2048LL * 2048, 2048LL * 1024);
}

// round 6
// speedup vs baseline: 2.1775x; 1.6168x over previous
#include <cuda_runtime.h>
#include <cuda_fp16.h>
#include <cstdint>

#define DI __device__ __forceinline__

static constexpr int B_ = 4, H_ = 8, S_ = 2048, D_ = 1024, KQ_ = 128;

// ---------------- scratch (device globals; no allocations allowed) ----------------
__device__ __half g_MT[(size_t)H_ * D_ * D_];    //  16 MB  M^T[h][j][d]
__device__ __half g_TWo[(size_t)H_ * D_ * D_];   //  16 MB  Wo^T per head [h][j][v]
__device__ __half g_WvH[(size_t)H_ * D_ * D_];   //  16 MB  Wv fp16 [h][d][v]
__device__ __half g_TWq[(size_t)H_ * KQ_ * D_];  //   2 MB  Wq^T [h][kq][d]
__device__ __half g_TWk[(size_t)H_ * KQ_ * D_];  //   2 MB
__device__ __half g_zh[(size_t)B_ * S_ * D_];    //  16 MB
__device__ __half g_yh[(size_t)B_ * S_ * D_];    //  16 MB
__device__ __half g_Qh[(size_t)B_ * H_ * S_ * KQ_];  // 16 MB
__device__ __half g_Kh[(size_t)B_ * H_ * S_ * KQ_];  // 16 MB
__device__ __half g_UT[(size_t)B_ * H_ * D_ * S_];   // 128 MB U^T[b,h][j][t]
__device__ float g_P[(size_t)B_ * H_ * S_ * S_];     // 512 MB scores fp32 / P fp16 packed
__device__ float g_cvec[D_];
__device__ float g_cpart[32 * D_];

// ---------------- helpers ----------------
DI uint32_t smem_u32(const void* p) {
    uint32_t a;
    asm("{ .reg .u64 t; cvta.to.shared.u64 t, %1; cvt.u32.u64 %0, t; }" : "=r"(a) : "l"(p));
    return a;
}
DI void mma_f16(float c[4], uint32_t a0, uint32_t a1, uint32_t a2, uint32_t a3,
                uint32_t b0, uint32_t b1) {
    asm volatile(
        "mma.sync.aligned.m16n8k16.row.col.f32.f16.f16.f32 "
        "{%0,%1,%2,%3}, {%4,%5,%6,%7}, {%8,%9}, {%0,%1,%2,%3};"
        : "+f"(c[0]), "+f"(c[1]), "+f"(c[2]), "+f"(c[3])
        : "r"(a0), "r"(a1), "r"(a2), "r"(a3), "r"(b0), "r"(b1));
}
DI void ldsm4(uint32_t r[4], uint32_t a) {
    asm volatile("ldmatrix.sync.aligned.m8n8.x4.shared.b16 {%0,%1,%2,%3}, [%4];"
                 : "=r"(r[0]), "=r"(r[1]), "=r"(r[2]), "=r"(r[3]) : "r"(a));
}
DI void cp16(uint32_t d, const void* s) {
    asm volatile("cp.async.cg.shared.global [%0], [%1], 16;" :: "r"(d), "l"(s));
}
DI void cp_commit() { asm volatile("cp.async.commit_group;" ::: "memory"); }

DI void cwrite(__half* p, float a, float b) {
    *reinterpret_cast<__half2*>(p) = __floats2half2_rn(a, b);
}
DI void cwrite(float* p, float a, float b) {
    *reinterpret_cast<float2*>(p) = make_float2(a, b);
}

// ======================= fp16 NT GEMM, cp.async 3-stage =======================
// C = alpha * A @ B^T + bias.  A [M,K] fp16, B [N,K] fp16, C fp32 or fp16.
// CTA 128x128, 256 threads, warp 64x32.  K in chunks of 32 halves.
// SMEM tiles 128 rows x 32 halves; 16B chunk (r,c) at p = r*4 + (c ^ ((r>>1)&3)).
// z = blockIdx.z; z1=z/Z2, z2=z%Z2; base offset z1*s?1 + z2*s?2 (element units).
// head-fused K: chunk c -> h = c>>hshift (offset h*s?h), k-off (c&hmask)*32.
template <typename CT>
__global__ __launch_bounds__(256, 2) void nt_gemm(
    const __half* __restrict__ Ag, const __half* __restrict__ Bg,
    CT* __restrict__ Cg, const float* __restrict__ bias,
    int kchunks, int lda, int ldb, int ldc,
    long long sA1, long long sA2, long long sB1, long long sB2,
    long long sC1, long long sC2, int Z2, int sbias2, float alpha,
    int hshift, long long sAh, long long sBh)
{
    __shared__ __align__(128) uint32_t sAs[3][2048];   // 3 stages x 8KB
    __shared__ __align__(128) uint32_t sBs[3][2048];

    const int tid = threadIdx.x, lane = tid & 31, wid = tid >> 5;
    const int wm = (wid & 1) * 64, wn = (wid >> 1) * 32;
    const int g = lane >> 2, q = lane & 3;

    const int z = blockIdx.z, z1 = z / Z2, z2 = z % Z2;
    const __half* A = Ag + z1 * sA1 + z2 * sA2;
    const __half* Bp = Bg + z1 * sB1 + z2 * sB2;
    CT* C = Cg + z1 * sC1 + z2 * sC2;
    const int bm = blockIdx.y * 128, bn = blockIdx.x * 128;

    // ---- loader geometry: 2 x 16B cp.async per operand per thread ----
    uint32_t dst[2];
    long long aoff[2], boff[2];
#pragma unroll
    for (int i = 0; i < 2; i++) {
        int qid = tid + i * 256;
        int lr = qid >> 2, lc = qid & 3;
        dst[i] = (uint32_t)((lr * 4 + (lc ^ ((lr >> 1) & 3))) << 4);
        aoff[i] = (long long)(bm + lr) * lda + lc * 8;
        boff[i] = (long long)(bn + lr) * ldb + lc * 8;
    }

    const uint32_t sAb = smem_u32(&sAs[0][0]);
    const uint32_t sBb = smem_u32(&sBs[0][0]);

    // ---- ldmatrix per-lane geometry ----
    const int l15 = lane & 15, hs = lane >> 4;
    uint32_t arow[4], axor[4], brow[2], bxor[2];
#pragma unroll
    for (int mt = 0; mt < 4; mt++) {
        int rr = wm + mt * 16 + l15;
        arow[mt] = (uint32_t)(rr * 64);
        axor[mt] = (uint32_t)((rr >> 1) & 3);
    }
#pragma unroll
    for (int np = 0; np < 2; np++) {
        int nn = wn + np * 16 + l15;
        brow[np] = (uint32_t)(nn * 64);
        bxor[np] = (uint32_t)((nn >> 1) & 3);
    }

    float acc[4][4][4];
#pragma unroll
    for (int i = 0; i < 4; i++)
#pragma unroll
        for (int j = 0; j < 4; j++)
#pragma unroll
            for (int k = 0; k < 4; k++) acc[i][j][k] = 0.f;

    const int hmask = (hshift < 30) ? ((1 << hshift) - 1) : 0x3FFFFFFF;

    auto issue = [&](int c, int st) {
        const __half* Ac = A + (long long)(c >> hshift) * sAh + (c & hmask) * 32;
        const __half* Bc = Bp + (long long)(c >> hshift) * sBh + (c & hmask) * 32;
        const uint32_t a0 = sAb + st * 8192, b0 = sBb + st * 8192;
#pragma unroll
        for (int i = 0; i < 2; i++) {
            cp16(a0 + dst[i], Ac + aoff[i]);
            cp16(b0 + dst[i], Bc + boff[i]);
        }
        cp_commit();
    };

    issue(0, 0);
    issue(1, 1);

    for (int c = 0; c < kchunks; c++) {
        if (c + 1 < kchunks)
            asm volatile("cp.async.wait_group 1;" ::: "memory");
        else
            asm volatile("cp.async.wait_group 0;" ::: "memory");
        __syncthreads();
        if (c + 2 < kchunks) issue(c + 2, (c + 2) % 3);

        const int st = c % 3;
        const uint32_t aB = sAb + st * 8192, bB = sBb + st * 8192;
#pragma unroll
        for (int s = 0; s < 2; s++) {
            uint32_t af[4][4], bf[4][2];
            const uint32_t cc = (uint32_t)(2 * s + hs);
#pragma unroll
            for (int mt = 0; mt < 4; mt++)
                ldsm4(af[mt], aB + arow[mt] + ((cc ^ axor[mt]) << 4));
#pragma unroll
            for (int np = 0; np < 2; np++) {
                uint32_t t4[4];
                ldsm4(t4, bB + brow[np] + ((cc ^ bxor[np]) << 4));
                bf[2 * np][0] = t4[0];
                bf[2 * np][1] = t4[2];
                bf[2 * np + 1][0] = t4[1];
                bf[2 * np + 1][1] = t4[3];
            }
#pragma unroll
            for (int mt = 0; mt < 4; mt++)
#pragma unroll
                for (int nt = 0; nt < 4; nt++)
                    mma_f16(acc[mt][nt], af[mt][0], af[mt][1], af[mt][2], af[mt][3],
                            bf[nt][0], bf[nt][1]);
        }
    }

    // ---- epilogue ----
    const float* bp = bias ? bias + (long long)z2 * sbias2 : nullptr;
#pragma unroll
    for (int mt = 0; mt < 4; mt++) {
#pragma unroll
        for (int nt = 0; nt < 4; nt++) {
            int r = bm + wm + mt * 16 + g;
            int cc = bn + wn + nt * 8 + q * 2;
            float b0v = bp ? bp[cc] : 0.f;
            float b1v = bp ? bp[cc + 1] : 0.f;
            cwrite(C + (long long)r * ldc + cc,
                   alpha * acc[mt][nt][0] + b0v, alpha * acc[mt][nt][1] + b1v);
            cwrite(C + (long long)(r + 8) * ldc + cc,
                   alpha * acc[mt][nt][2] + b0v, alpha * acc[mt][nt][3] + b1v);
        }
    }
}

// ---------------- fp32 -> fp16 convert ----------------
__global__ void conv_f2h(const float* __restrict__ in, __half* __restrict__ out, int n4) {
    int i = blockIdx.x * 256 + threadIdx.x;
    if (i < n4) {
        float4 v = reinterpret_cast<const float4*>(in)[i];
        __half2 h0 = __floats2half2_rn(v.x, v.y);
        __half2 h1 = __floats2half2_rn(v.z, v.w);
        uint2 u;
        u.x = *reinterpret_cast<uint32_t*>(&h0);
        u.y = *reinterpret_cast<uint32_t*>(&h1);
        reinterpret_cast<uint2*>(out)[i] = u;
    }
}

// ---------------- per-head transpose fp32 [R,C] -> fp16 [C,R] ----------------
__global__ void trans_f2h(const float* __restrict__ in, __half* __restrict__ out,
                          int R, int C) {
    __shared__ float t[32][33];
    const float* ip = in + (size_t)blockIdx.z * R * C;
    __half* op = out + (size_t)blockIdx.z * R * C;
    int bx = blockIdx.x * 32, by = blockIdx.y * 32;
    int tx = threadIdx.x & 31, ty = threadIdx.x >> 5;
#pragma unroll
    for (int j = 0; j < 32; j += 8)
        t[ty + j][tx] = ip[(size_t)(by + ty + j) * C + bx + tx];
    __syncthreads();
#pragma unroll
    for (int j = 0; j < 32; j += 8)
        op[(size_t)(bx + ty + j) * R + by + tx] = __float2half(t[tx][ty + j]);
}

// ---------------- folded bias: cvec = bo + bv_flat @ Wo ----------------
__global__ void cvec_partial_k(const float* __restrict__ bv, const float* __restrict__ Wo) {
    int j = blockIdx.x * 256 + threadIdx.x;
    int r0 = blockIdx.y * 256;
    float acc = 0.f;
    for (int r = r0; r < r0 + 256; r++) acc += bv[r] * Wo[(size_t)r * D_ + j];
    g_cpart[blockIdx.y * D_ + j] = acc;
}
__global__ void cvec_final_k(const float* __restrict__ bo) {
    int j = blockIdx.x * 256 + threadIdx.x;
    float acc = bo[j];
    for (int r = 0; r < 32; r++) acc += g_cpart[r * D_ + j];
    g_cvec[j] = acc;
}

// ------- row softmax: fp32 scores -> fp16 P packed into the row's first half -------
__global__ __launch_bounds__(256) void softmax_k() {
    float* row = g_P + (size_t)blockIdx.x * S_;
    int tid = threadIdx.x;
    float4 u = *(const float4*)(row + tid * 8);
    float4 w = *(const float4*)(row + tid * 8 + 4);
    float v[8] = {u.x, u.y, u.z, u.w, w.x, w.y, w.z, w.w};

    float mx = -1e30f;
#pragma unroll
    for (int i = 0; i < 8; i++) mx = fmaxf(mx, v[i]);
#pragma unroll
    for (int o = 16; o > 0; o >>= 1) mx = fmaxf(mx, __shfl_xor_sync(0xffffffffu, mx, o));
    __shared__ float red[8];
    if ((tid & 31) == 0) red[tid >> 5] = mx;
    __syncthreads();
    mx = red[0];
#pragma unroll
    for (int wi = 1; wi < 8; wi++) mx = fmaxf(mx, red[wi]);

    float s = 0.f;
#pragma unroll
    for (int i = 0; i < 8; i++) {
        v[i] = exp2f((v[i] - mx) * 1.4426950408889634f);
        s += v[i];
    }
#pragma unroll
    for (int o = 16; o > 0; o >>= 1) s += __shfl_xor_sync(0xffffffffu, s, o);
    __syncthreads();
    if ((tid & 31) == 0) red[tid >> 5] = s;
    __syncthreads();
    s = 0.f;
#pragma unroll
    for (int wi = 0; wi < 8; wi++) s += red[wi];
    float inv = 1.f / s;

    __half2 p0 = __floats2half2_rn(v[0] * inv, v[1] * inv);
    __half2 p1 = __floats2half2_rn(v[2] * inv, v[3] * inv);
    __half2 p2 = __floats2half2_rn(v[4] * inv, v[5] * inv);
    __half2 p3 = __floats2half2_rn(v[6] * inv, v[7] * inv);
    uint4 o;
    o.x = *reinterpret_cast<uint32_t*>(&p0);
    o.y = *reinterpret_cast<uint32_t*>(&p1);
    o.z = *reinterpret_cast<uint32_t*>(&p2);
    o.w = *reinterpret_cast<uint32_t*>(&p3);
    *reinterpret_cast<uint4*>(reinterpret_cast<__half*>(row) + tid * 8) = o;
}

// ---------------- launch ----------------
extern "C" void kernel_launch(void* const* d_in, const int* in_sizes, int n_in,
                              void* d_out, int out_size) {
    const float* z  = (const float*)d_in[0];
    const float* y  = (const float*)d_in[1];
    const float* Wq = (const float*)d_in[2];
    const float* bq = (const float*)d_in[3];
    const float* Wk = (const float*)d_in[4];
    const float* bk = (const float*)d_in[5];
    const float* Wv = (const float*)d_in[6];
    const float* bv = (const float*)d_in[7];
    const float* Wo = (const float*)d_in[8];
    const float* bo = (const float*)d_in[9];
    float* out = (float*)d_out;

    __half *pMT, *pTWo, *pWvH, *pTWq, *pTWk, *pzh, *pyh, *pQh, *pKh, *pUT;
    float *pP, *pc;
    cudaGetSymbolAddress((void**)&pMT, g_MT);
    cudaGetSymbolAddress((void**)&pTWo, g_TWo);
    cudaGetSymbolAddress((void**)&pWvH, g_WvH);
    cudaGetSymbolAddress((void**)&pTWq, g_TWq);
    cudaGetSymbolAddress((void**)&pTWk, g_TWk);
    cudaGetSymbolAddress((void**)&pzh, g_zh);
    cudaGetSymbolAddress((void**)&pyh, g_yh);
    cudaGetSymbolAddress((void**)&pQh, g_Qh);
    cudaGetSymbolAddress((void**)&pKh, g_Kh);
    cudaGetSymbolAddress((void**)&pUT, g_UT);
    cudaGetSymbolAddress((void**)&pP, g_P);
    cudaGetSymbolAddress((void**)&pc, g_cvec);

    // -- pre-pass: converts + transposes + folded bias --
    conv_f2h<<<(B_ * S_ * D_ / 4 + 255) / 256, 256>>>(z, pzh, B_ * S_ * D_ / 4);
    conv_f2h<<<(B_ * S_ * D_ / 4 + 255) / 256, 256>>>(y, pyh, B_ * S_ * D_ / 4);
    conv_f2h<<<(H_ * D_ * D_ / 4 + 255) / 256, 256>>>(Wv, pWvH, H_ * D_ * D_ / 4);
    trans_f2h<<<dim3(32, 32, 8), 256>>>(Wo, pTWo, 1024, 1024);  // [h][v][j] -> [h][j][v]
    trans_f2h<<<dim3(4, 32, 8), 256>>>(Wq, pTWq, 1024, 128);    // [h][d][kq] -> [h][kq][d]
    trans_f2h<<<dim3(4, 32, 8), 256>>>(Wk, pTWk, 1024, 128);
    cvec_partial_k<<<dim3(4, 32), 256>>>(bv, Wo);
    cvec_final_k<<<4, 256>>>(bo);

    // 1) M^T[h] = TWo[h] @ WvH[h]^T              [h] x (1024,1024,1024)
    nt_gemm<__half><<<dim3(8, 8, 8), 256>>>(
        pTWo, pWvH, pMT, nullptr, 32, 1024, 1024, 1024,
        0, (long long)D_ * D_, 0, (long long)D_ * D_, 0, (long long)D_ * D_,
        8, 0, 1.f, 30, 0, 0);

    // 2) Q[b,h] = yh[b] @ TWq[h]^T + bq          [b,h] x (2048,128,1024)
    nt_gemm<__half><<<dim3(1, 16, 32), 256>>>(
        pyh, pTWq, pQh, bq, 32, 1024, 1024, 128,
        (long long)S_ * D_, 0, 0, (long long)KQ_ * D_,
        (long long)H_ * S_ * KQ_, (long long)S_ * KQ_, 8, 128, 1.f, 30, 0, 0);

    // 3) K[b,h] = zh[b] @ TWk[h]^T + bk
    nt_gemm<__half><<<dim3(1, 16, 32), 256>>>(
        pzh, pTWk, pKh, bk, 32, 1024, 1024, 128,
        (long long)S_ * D_, 0, 0, (long long)KQ_ * D_,
        (long long)H_ * S_ * KQ_, (long long)S_ * KQ_, 8, 128, 1.f, 30, 0, 0);

    // 4) U^T[b,h] = MT[h] @ zh[b]^T              [b,h] x (1024,2048,1024)
    nt_gemm<__half><<<dim3(16, 8, 32), 256>>>(
        pMT, pzh, pUT, nullptr, 32, 1024, 1024, 2048,
        0, (long long)D_ * D_, (long long)S_ * D_, 0,
        (long long)H_ * D_ * S_, (long long)D_ * S_, 8, 0, 1.f, 30, 0, 0);

    // 5) scores = (Qh @ Kh^T) / sqrt(128)        [b,h] x (2048,2048,128), fp32 out
    nt_gemm<float><<<dim3(16, 16, 32), 256>>>(
        pQh, pKh, pP, nullptr, 4, 128, 128, 2048,
        (long long)H_ * S_ * KQ_, (long long)S_ * KQ_,
        (long long)H_ * S_ * KQ_, (long long)S_ * KQ_,
        (long long)H_ * S_ * S_, (long long)S_ * S_,
        8, 0, 0.08838834764831845f, 30, 0, 0);

    // 6) softmax rows (fp32 -> fp16 packed)
    softmax_k<<<B_ * H_ * S_, 256>>>();

    // 7) out = sum_h P_h @ UT_h^T + cvec         [b] x (2048,1024,K=8*2048) head-fused
    nt_gemm<float><<<dim3(8, 16, 4), 256>>>(
        (const __half*)pP, pUT, out, pc, 512, 2 * S_, 2048, 1024,
        0, (long long)H_ * S_ * 2 * S_, 0, (long long)H_ * D_ * S_,
        0, (long long)S_ * D_, 4, 0, 1.f,
        6, (long long)S_ * 2 * S_, (long long)D_ * S_);
}